// round 15
// baseline (speedup 1.0000x reference)
#include <cuda_runtime.h>
#include <cuda_bf16.h>
#include <math.h>
#include <stdint.h>

#define NN 20000
#define NE 320000
#define CC 14
#define TE128 (NE/128)              // 2500
#define TN128 ((NN+127)/128)        // 157

// ---------------- scratch ----------------
__device__ __align__(16) float g_radial[(size_t)NE*128];  // bf16 [E][256] = radial*rinv
__device__ __align__(16) float g_ef1[(size_t)NE*64];      // bf16 [E][128] e1 out
__device__ float g_rinv[NE];
__device__ float g_csum[NN];
__device__ float g_pool3[NN*3];
__device__ float g_aggsum[(size_t)NN*128];
__device__ float g_cnt_col[NN];
__device__ float g_xsum[NN*CC*3];
__device__ float g_cnt_row[NN];
__device__ __align__(16) float g_hbf[NN*64];      // bf16 h
__device__ __align__(16) float g_abf[NN*112];     // bf16 attr
__device__ __align__(16) float g_waug[128*272];   // bf16 [128][544] augmented e1 weight
__device__ __align__(16) float g_we2[128*64];     // bf16 e2W
__device__ __align__(16) float g_wc1[128*64];     // bf16 c1W

__device__ __forceinline__ float sigm(float v){ return 1.f/(1.f+__expf(-v)); }
__device__ __forceinline__ float silu_(float v){ return v*sigm(v); }
__device__ __forceinline__ uint32_t pk2(float lo, float hi){
    __nv_bfloat162 t = __floats2bfloat162_rn(lo, hi);
    return *(uint32_t*)&t;
}
__device__ __forceinline__ void mma16(float* c, const uint32_t* a, const uint32_t* b){
    asm volatile("mma.sync.aligned.m16n8k16.row.col.f32.bf16.bf16.f32 "
        "{%0,%1,%2,%3}, {%4,%5,%6,%7}, {%8,%9}, {%0,%1,%2,%3};"
        : "+f"(c[0]),"+f"(c[1]),"+f"(c[2]),"+f"(c[3])
        : "r"(a[0]),"r"(a[1]),"r"(a[2]),"r"(a[3]), "r"(b[0]),"r"(b[1]));
}
__device__ __forceinline__ void ldm4(uint32_t* r, uint32_t addr){
    asm volatile("ldmatrix.sync.aligned.m8n8.x4.shared.b16 {%0,%1,%2,%3}, [%4];"
        : "=r"(r[0]),"=r"(r[1]),"=r"(r[2]),"=r"(r[3]) : "r"(addr));
}
__device__ __forceinline__ void red2(float* addr, float a, float b){
    asm volatile("red.global.add.v2.f32 [%0], {%1, %2};"
        :: "l"(addr), "f"(a), "f"(b) : "memory");
}
__device__ __forceinline__ uint32_t smem_u32(const void* p){
    uint32_t a;
    asm("{ .reg .u64 t; cvta.to.shared.u64 t, %1; cvt.u32.u64 %0, t; }" : "=r"(a) : "l"(p));
    return a;
}
__device__ __forceinline__ void cp16(uint32_t dst, const void* src){
    asm volatile("cp.async.ca.shared.global [%0], [%1], 16;" :: "r"(dst), "l"(src) : "memory");
}
#define CPC() asm volatile("cp.async.commit_group;" ::: "memory")

// ---------------- merged prep ----------------
__global__ void k_prepall(const float* __restrict__ x, const float* __restrict__ cw,
                          const float* __restrict__ h, const float* __restrict__ attr,
                          const float* __restrict__ e2W, const float* __restrict__ c1W){
    long long i = (long long)blockIdx.x*256 + threadIdx.x;
    const long long ZA = (long long)NN*128;
    const long long ZB = ZA + NN;
    const long long ZD = ZB + (long long)NN*42;
    const long long ZE = ZD + NN;
    const long long HC = ZE + (long long)NN*64;
    const long long AC = HC + (long long)NN*112;
    const long long WC = AC + 2*128*64;
    const long long PR = WC + NN;
    if(i < ZA) g_aggsum[i]=0.f;
    else if(i < ZB) g_cnt_col[i-ZA]=0.f;
    else if(i < ZD) g_xsum[i-ZB]=0.f;
    else if(i < ZE) g_cnt_row[i-ZD]=0.f;
    else if(i < HC){ long long j=i-ZE; float2 v=((const float2*)h)[j];
        ((uint32_t*)g_hbf)[j]=pk2(v.x,v.y); }
    else if(i < AC){ long long j=i-HC; float2 v=((const float2*)attr)[j];
        ((uint32_t*)g_abf)[j]=pk2(v.x,v.y); }
    else if(i < WC){ long long j=i-AC;
        if(j < 128*64){ float2 v=((const float2*)e2W)[j]; ((uint32_t*)g_we2)[j]=pk2(v.x,v.y); }
        else { long long k=j-128*64; float2 v=((const float2*)c1W)[k]; ((uint32_t*)g_wc1)[k]=pk2(v.x,v.y); }
    }
    else if(i < PR){
        int n = (int)(i-WC);
        float cnt=0.f, px=0.f, py=0.f, pz=0.f;
        #pragma unroll
        for(int k=0;k<CC;k++){
            float w = cw[n*CC+k];
            if(w != 0.f){
                cnt += 1.f;
                const float* xp = &x[(n*CC+k)*3];
                px += xp[0]; py += xp[1]; pz += xp[2];
            }
        }
        g_csum[n] = cnt;
        float inv = 1.f/cnt;
        g_pool3[n*3+0]=px*inv; g_pool3[n*3+1]=py*inv; g_pool3[n*3+2]=pz*inv;
    }
}
#define PREP_TOTAL ((long long)NN*128 + NN + (long long)NN*42 + NN + (long long)NN*64 + (long long)NN*112 + 2*128*64 + NN)

// ---------------- build augmented e1 weight ----------------
__global__ void k_waug(const float* __restrict__ e1W, const float* __restrict__ radW,
                       const float* __restrict__ radB){
    __shared__ float s[128];
    int n = blockIdx.x, tid = threadIdx.x;
    if(tid < 128) s[tid] = e1W[n*384 + 256 + tid];
    __syncthreads();
    uint32_t* out = (uint32_t*)g_waug + n*272;
    if(tid < 128) out[tid] = pk2(e1W[n*384 + 2*tid], e1W[n*384 + 2*tid + 1]);
    else if(tid-128 < 128){
        int kpl = tid-128;
        int kk = 2*kpl;
        float d0=0.f, d1=0.f;
        #pragma unroll 4
        for(int j=0;j<128;j++){
            float sj = s[j];
            d0 += sj*radW[j*256+kk];
            d1 += sj*radW[j*256+kk+1];
        }
        out[128+kpl] = pk2(d0,d1);
    }
    if(tid==0){
        float bc=0.f;
        for(int j=0;j<128;j++) bc += s[j]*radB[j];
        out[256] = pk2(bc, 0.f);
    }
    if(tid>=1 && tid<16) out[256+tid] = 0u;
}

// ---------------- geometry via tensor cores ---------------
__global__ void __launch_bounds__(256) k_geom(const float* __restrict__ x,
        const int* __restrict__ row, const int* __restrict__ col,
        const float* __restrict__ cw){
    __shared__ float sX[8][88];
    __shared__ float sCW[8][32];
    __shared__ uint32_t sAR[8][112];
    __shared__ uint32_t sAC[8][112];
    __shared__ float sT[8][256];
    const int warp=threadIdx.x>>5, lane=threadIdx.x&31;
    const int e = blockIdx.x*8 + warp;
    if(e >= NE) return;
    const int r=row[e], c=col[e];
    const uint32_t* ab=(const uint32_t*)g_abf;
    if(lane<CC){ sCW[warp][lane]=cw[r*CC+lane]; sCW[warp][16+lane]=cw[c*CC+lane]; }
    if(lane==0){ atomicAdd(&g_cnt_row[r],1.f); atomicAdd(&g_cnt_col[c],1.f); }
    for(int i=lane;i<42;i+=32){ sX[warp][i]=x[r*42+i]; sX[warp][44+i]=x[c*42+i]; }
    for(int i=lane;i<112;i+=32){ sAR[warp][i]=ab[r*112+i]; sAC[warp][i]=ab[c*112+i]; }
    __syncwarp();
    const int r4=lane>>2, c4=lane&3;
    auto dist=[&](int i,int j)->float{
        if(i>=CC||j>=CC) return 0.f;
        float dx=sX[warp][i*3]  -sX[warp][44+j*3];
        float dy=sX[warp][i*3+1]-sX[warp][44+j*3+1];
        float dz=sX[warp][i*3+2]-sX[warp][44+j*3+2];
        return sqrtf(dx*dx+dy*dy+dz*dz);
    };
    uint32_t aD[4];
    {
        int j0=2*c4, j2=2*c4+8;
        aD[0]=pk2(dist(r4,j0),  dist(r4,j0+1));
        aD[1]=pk2(dist(r4+8,j0),dist(r4+8,j0+1));
        aD[2]=pk2(dist(r4,j2),  dist(r4,j2+1));
        aD[3]=pk2(dist(r4+8,j2),dist(r4+8,j2+1));
    }
    auto acv=[&](int j,int b)->float{
        if(j>=CC) return 0.f;
        uint32_t w = sAC[warp][j*8 + (b>>1)];
        __nv_bfloat162 t=*(__nv_bfloat162*)&w;
        float v=(b&1)? __high2float(t): __low2float(t);
        return v*sCW[warp][16+j];
    };
    float T0[4]={0,0,0,0}, T1[4]={0,0,0,0};
    {
        uint32_t b0[2], b1[2];
        b0[0]=pk2(acv(2*c4,r4),    acv(2*c4+1,r4));
        b0[1]=pk2(acv(2*c4+8,r4),  acv(2*c4+9,r4));
        b1[0]=pk2(acv(2*c4,r4+8),  acv(2*c4+1,r4+8));
        b1[1]=pk2(acv(2*c4+8,r4+8),acv(2*c4+9,r4+8));
        mma16(T0,aD,b0);
        mma16(T1,aD,b1);
    }
    {
        float* st=sT[warp];
        st[r4*16+2*c4]       =T0[0]; st[r4*16+2*c4+1]     =T0[1];
        st[(r4+8)*16+2*c4]   =T0[2]; st[(r4+8)*16+2*c4+1] =T0[3];
        st[r4*16+8+2*c4]     =T1[0]; st[r4*16+8+2*c4+1]   =T1[1];
        st[(r4+8)*16+8+2*c4] =T1[2]; st[(r4+8)*16+8+2*c4+1]=T1[3];
    }
    __syncwarp();
    auto arv=[&](int i,int a)->float{
        if(i>=CC) return 0.f;
        uint32_t w = sAR[warp][i*8 + (a>>1)];
        __nv_bfloat162 t=*(__nv_bfloat162*)&w;
        float v=(a&1)? __high2float(t): __low2float(t);
        return v*sCW[warp][i];
    };
    uint32_t aR[4];
    aR[0]=pk2(arv(2*c4,r4),    arv(2*c4+1,r4));
    aR[1]=pk2(arv(2*c4,r4+8),  arv(2*c4+1,r4+8));
    aR[2]=pk2(arv(2*c4+8,r4),  arv(2*c4+9,r4));
    aR[3]=pk2(arv(2*c4+8,r4+8),arv(2*c4+9,r4+8));
    float R0[4]={0,0,0,0}, R1[4]={0,0,0,0};
    {
        const float* st=sT[warp];
        uint32_t b0[2], b1[2];
        b0[0]=pk2(st[(2*c4)*16+r4],    st[(2*c4+1)*16+r4]);
        b0[1]=pk2(st[(2*c4+8)*16+r4],  st[(2*c4+9)*16+r4]);
        b1[0]=pk2(st[(2*c4)*16+r4+8],  st[(2*c4+1)*16+r4+8]);
        b1[1]=pk2(st[(2*c4+8)*16+r4+8],st[(2*c4+9)*16+r4+8]);
        mma16(R0,aR,b0);
        mma16(R1,aR,b1);
    }
    float sq = R0[0]*R0[0]+R0[1]*R0[1]+R0[2]*R0[2]+R0[3]*R0[3]
             + R1[0]*R1[0]+R1[1]*R1[1]+R1[2]*R1[2]+R1[3]*R1[3];
    #pragma unroll
    for(int o=16;o>0;o>>=1) sq += __shfl_xor_sync(0xffffffffu,sq,o);
    float rinv = 1.f/(sqrtf(sq)+1.f);
    uint32_t* go=(uint32_t*)g_radial + (size_t)e*128;
    go[r4*8 + c4]         = pk2(R0[0]*rinv, R0[1]*rinv);
    go[(r4+8)*8 + c4]     = pk2(R0[2]*rinv, R0[3]*rinv);
    go[r4*8 + 4 + c4]     = pk2(R1[0]*rinv, R1[1]*rinv);
    go[(r4+8)*8 + 4 + c4] = pk2(R1[2]*rinv, R1[3]*rinv);
    if(lane==0) g_rinv[e]=rinv;
}

// ===== e1 GEMM: K=544, cp.async 4-stage pipeline, [m][20] layout, ldmatrix =====
#define E1SM 81920
__global__ void __launch_bounds__(256,2) k_e1(
    const float* __restrict__ e1B, const int* __restrict__ rowi,
    const int* __restrict__ coli, int tiles)
{
    extern __shared__ uint32_t dsm[];
    __shared__ int sRow[128], sCol[128];
    __shared__ float sBias[128];
    const int tid=threadIdx.x, wid=tid>>5, lane=tid&31;
    const int warpM=(wid&3)*32, warpN=(wid>>2)*64;
    const int ee=tid>>1, q=tid&1;
    const int r4=lane>>2, c4=lane&3;
    const uint32_t* hbf=(const uint32_t*)g_hbf;
    const uint32_t* rad=(const uint32_t*)g_radial;
    const uint32_t* waug=(const uint32_t*)g_waug;
    uint32_t* Obf=(uint32_t*)g_ef1;
    if(tid<128) sBias[tid]=e1B[tid];
    const uint32_t smB = smem_u32(dsm);
    const uint32_t aoffB = (uint32_t)(ee*20 + q*8)*4u;
    // ldmatrix per-lane base offsets (bytes)
    const uint32_t aB1 = (uint32_t)((warpM + (lane&15))*20 + ((lane&16)?4:0))*4u;
    const uint32_t bB1 = (uint32_t)((warpN + ((lane>>4)<<3) + (lane&7))*20 + ((lane&8)?4:0))*4u;

    for(int tile=blockIdx.x; tile<tiles; tile+=gridDim.x){
        if(tid<128){ sRow[tid]=rowi[tile*128+tid]; sCol[tid]=coli[tile*128+tid]; }
        __syncthreads();
        const int rg = tile*128 + ee;

        auto issue=[&](int kt){
            const int s = kt&3;
            const uint32_t dA = smB + (uint32_t)s*10240u + aoffB;
            const uint32_t dW = smB + 40960u + (uint32_t)s*10240u + aoffB;
            const uint32_t* wsrc = &waug[ee*272 + kt*16 + q*8];
            cp16(dW, wsrc); cp16(dW+16, wsrc+4);
            const int kp = kt*16 + q*8;
            if(kp < 256){
                const uint32_t* asrc;
                if(kp < 64)       asrc = &hbf[sRow[ee]*64 + kp];
                else if(kp < 128) asrc = &hbf[sCol[ee]*64 + (kp-64)];
                else              asrc = &rad[(size_t)rg*128 + (kp-128)];
                cp16(dA, asrc); cp16(dA+16, asrc+4);
            } else {
                uint32_t* sa = dsm + s*2560 + ee*20 + q*8;
                sa[0] = (q==0)? pk2(g_rinv[rg],0.f) : 0u;
                #pragma unroll
                for(int j=1;j<8;j++) sa[j]=0u;
            }
        };

        float acc[2][8][4];
        #pragma unroll
        for(int am=0;am<2;am++)
            #pragma unroll
            for(int bn=0;bn<8;bn++)
                #pragma unroll
                for(int i=0;i<4;i++) acc[am][bn][i]=0.f;

        issue(0); CPC(); issue(1); CPC(); issue(2); CPC();

        #pragma unroll 1
        for(int kt=0; kt<17; kt++){
            asm volatile("cp.async.wait_group 2;" ::: "memory");
            __syncthreads();
            if(kt+3 <= 16) issue(kt+3);
            CPC();
            const uint32_t smA = smB + (uint32_t)(kt&3)*10240u;
            const uint32_t smW = smB + 40960u + (uint32_t)(kt&3)*10240u;
            #pragma unroll
            for(int g=0; g<2; g++){
                uint32_t av[2][4], bv[4][4];
                ldm4(av[0], smA + aB1 + (uint32_t)(g*8)*4u);
                ldm4(av[1], smA + aB1 + (uint32_t)(16*20 + g*8)*4u);
                #pragma unroll
                for(int bb=0;bb<4;bb++)
                    ldm4(bv[bb], smW + bB1 + (uint32_t)(bb*16*20 + g*8)*4u);
                #pragma unroll
                for(int am=0;am<2;am++)
                    #pragma unroll
                    for(int bn=0;bn<8;bn++)
                        mma16(acc[am][bn], av[am], &bv[bn>>1][(bn&1)*2]);
            }
        }

        #pragma unroll
        for(int am=0;am<2;am++)
            #pragma unroll
            for(int hf=0;hf<2;hf++){
                int rl = warpM + am*16 + r4 + hf*8;
                int rgo = tile*128 + rl;
                uint32_t* op = &Obf[(size_t)rgo*64];
                #pragma unroll
                for(int bn=0;bn<8;bn++){
                    int c0 = warpN + bn*8 + c4*2;
                    float v0 = silu_(acc[am][bn][hf*2]   + sBias[c0]);
                    float v1 = silu_(acc[am][bn][hf*2+1] + sBias[c0+1]);
                    op[c0>>1] = pk2(v0, v1);
                }
            }
        __syncthreads();
    }
}

// ===== fused e2 + gate + agg + c1 + c2 + roller; row-major [m][68] + ldmatrix =====
#define E2SM 182080
__global__ void __launch_bounds__(256) k_e2c1(
    const float* __restrict__ e2B, const float* __restrict__ c1B,
    const float* __restrict__ c2Wf, const float* __restrict__ c2bf,
    const int* __restrict__ rowi, const int* __restrict__ coli,
    const float* __restrict__ attWg, const float* __restrict__ attbg,
    const float* __restrict__ x,
    float* __restrict__ agg, float* __restrict__ cnt, int tiles)
{
    extern __shared__ uint32_t dsm[];
    uint32_t* SA   = dsm;            // 2 x 128x68
    uint32_t* SW2  = dsm + 17408;    // 128x68
    uint32_t* SW3  = dsm + 26112;    // 128x68
    uint32_t* SEF  = dsm + 34816;    // 128x68 (phase C: sCh fp32 128x16)
    uint32_t* SC2P = dsm + 43520;    // 16x68
    int*   sRow   = (int*)(dsm + 44608);
    int*   sCol   = sRow + 128;
    float* sBias  = (float*)(sCol + 128);
    float* sBias2 = sBias + 128;
    float* sAtt   = sBias2 + 128;
    float* sDot   = sAtt + 128;      // 256
    float* scb    = sDot + 256;      // 16
    const int tid=threadIdx.x, wid=tid>>5, lane=tid&31;
    const int warpM=(wid&3)*32, warpN=(wid>>2)*64;
    const int r4=lane>>2, c4=lane&3;
    const uint32_t* Abf=(const uint32_t*)g_ef1;
    const uint32_t* W2g=(const uint32_t*)g_we2;
    const uint32_t* W3g=(const uint32_t*)g_wc1;
    const uint32_t uB = smem_u32(dsm);
    const uint32_t uSW2 = uB + 17408u*4u, uSW3 = uB + 26112u*4u;
    const uint32_t uSEF = uB + 34816u*4u, uSC2 = uB + 43520u*4u;
    const uint32_t aB2 = (uint32_t)((warpM + (lane&15))*68 + ((lane&16)?4:0))*4u;
    const uint32_t bB2 = (uint32_t)((warpN + ((lane>>4)<<3) + (lane&7))*68 + ((lane&8)?4:0))*4u;
    const uint32_t bC2 = (uint32_t)((((lane>>4)<<3) + (lane&7))*68 + ((lane&8)?4:0))*4u;

    for(int idx=tid; idx<128*64; idx+=256){
        int n = idx>>6, kp = idx&63;
        SW2[n*68+kp] = W2g[idx];
        SW3[n*68+kp] = W3g[idx];
    }
    for(int idx=tid; idx<16*64; idx+=256){
        int n = idx>>6, kp = idx&63;
        SC2P[n*68+kp] = (n<14)? pk2(c2Wf[n*128+2*kp], c2Wf[n*128+2*kp+1]) : 0u;
    }
    if(tid<16) scb[tid] = (tid<14)? c2bf[tid] : 0.f;
    if(tid<128){ sBias[tid]=e2B[tid]; sBias2[tid]=c1B[tid]; sAtt[tid]=attWg[tid]; }
    const float attb = attbg[0];

    auto ldAfull = [&](int t, uint4* v){
        const uint32_t* p = &Abf[(size_t)(t*128 + (tid>>1))*64 + (tid&1)*32];
        #pragma unroll
        for(int j=0;j<8;j++) v[j] = ((const uint4*)p)[j];
    };
    auto stsA = [&](int b, const uint4* v){
        uint4* base = (uint4*)&SA[b*8704 + (tid>>1)*68 + (tid&1)*32];
        #pragma unroll
        for(int j=0;j<8;j++) base[j] = v[j];
    };
    float acc[2][8][4];
    auto gemm128 = [&](uint32_t smA_, uint32_t smW_){
        #pragma unroll
        for(int g=0; g<8; g++){
            uint32_t av[2][4], bv[4][4];
            ldm4(av[0], smA_ + aB2 + (uint32_t)(g*8)*4u);
            ldm4(av[1], smA_ + aB2 + (uint32_t)(16*68 + g*8)*4u);
            #pragma unroll
            for(int bb=0;bb<4;bb++)
                ldm4(bv[bb], smW_ + bB2 + (uint32_t)(bb*16*68 + g*8)*4u);
            #pragma unroll
            for(int am=0;am<2;am++)
                #pragma unroll
                for(int bn=0;bn<8;bn++)
                    mma16(acc[am][bn], av[am], &bv[bn>>1][(bn&1)*2]);
        }
    };

    { uint4 v[8]; ldAfull(blockIdx.x, v); stsA(0, v); }
    int pb = 0;

    for(int tile=blockIdx.x; tile<tiles; tile+=gridDim.x){
        if(tid<128){ sRow[tid]=rowi[tile*128+tid]; sCol[tid]=coli[tile*128+tid]; }
        __syncthreads();
        int nt = tile + gridDim.x;
        bool pf = nt < tiles;
        uint4 an[8];
        if(pf) ldAfull(nt, an);

        #pragma unroll
        for(int am=0;am<2;am++)
            #pragma unroll
            for(int bn=0;bn<8;bn++)
                #pragma unroll
                for(int i=0;i<4;i++) acc[am][bn][i]=0.f;
        gemm128(uB + (uint32_t)pb*8704u*4u, uSW2);
        if(pf) stsA(pb^1, an);

        #pragma unroll
        for(int am=0;am<2;am++)
            #pragma unroll
            for(int bn=0;bn<8;bn++){
                int c0 = warpN + bn*8 + c4*2;
                float* a = acc[am][bn];
                a[0]=silu_(a[0]+sBias[c0]);   a[1]=silu_(a[1]+sBias[c0+1]);
                a[2]=silu_(a[2]+sBias[c0]);   a[3]=silu_(a[3]+sBias[c0+1]);
            }
        {
            float dot[2][2] = {{0.f,0.f},{0.f,0.f}};
            #pragma unroll
            for(int am=0;am<2;am++)
                #pragma unroll
                for(int bn=0;bn<8;bn++){
                    int c0 = warpN + bn*8 + c4*2;
                    float w0=sAtt[c0], w1=sAtt[c0+1];
                    dot[am][0] += acc[am][bn][0]*w0 + acc[am][bn][1]*w1;
                    dot[am][1] += acc[am][bn][2]*w0 + acc[am][bn][3]*w1;
                }
            #pragma unroll
            for(int am=0;am<2;am++)
                #pragma unroll
                for(int hf=0;hf<2;hf++){
                    dot[am][hf] += __shfl_xor_sync(0xffffffffu, dot[am][hf], 1);
                    dot[am][hf] += __shfl_xor_sync(0xffffffffu, dot[am][hf], 2);
                }
            if(c4==0){
                #pragma unroll
                for(int am=0;am<2;am++){
                    sDot[(wid>>2)*128 + warpM+am*16+r4]   = dot[am][0];
                    sDot[(wid>>2)*128 + warpM+am*16+r4+8] = dot[am][1];
                }
            }
            __syncthreads();
            #pragma unroll
            for(int am=0;am<2;am++)
                #pragma unroll
                for(int hf=0;hf<2;hf++){
                    int rl = warpM + am*16 + r4 + hf*8;
                    float g = sigm(sDot[rl] + sDot[128+rl] + attb);
                    #pragma unroll
                    for(int bn=0;bn<8;bn++){
                        acc[am][bn][hf*2]   *= g;
                        acc[am][bn][hf*2+1] *= g;
                    }
                }
        }
        #pragma unroll
        for(int am=0;am<2;am++)
            #pragma unroll
            for(int hf=0;hf<2;hf++){
                int rl = warpM + am*16 + r4 + hf*8;
                int cc = sCol[rl];
                float* ag = &agg[(size_t)cc*128];
                #pragma unroll
                for(int bn=0;bn<8;bn++){
                    int c0 = warpN + bn*8 + c4*2;
                    float v0 = acc[am][bn][hf*2], v1 = acc[am][bn][hf*2+1];
                    red2(ag+c0, v0, v1);
                    SEF[rl*68 + (c0>>1)] = pk2(v0, v1);
                }
            }
        __syncthreads();

        #pragma unroll
        for(int am=0;am<2;am++)
            #pragma unroll
            for(int bn=0;bn<8;bn++)
                #pragma unroll
                for(int i=0;i<4;i++) acc[am][bn][i]=0.f;
        gemm128(uSEF, uSW3);
        #pragma unroll
        for(int am=0;am<2;am++)
            #pragma unroll
            for(int hf=0;hf<2;hf++){
                int rl = warpM + am*16 + r4 + hf*8;
                #pragma unroll
                for(int bn=0;bn<8;bn++){
                    int c0 = warpN + bn*8 + c4*2;
                    float v0 = silu_(acc[am][bn][hf*2]   + sBias2[c0]);
                    float v1 = silu_(acc[am][bn][hf*2+1] + sBias2[c0+1]);
                    SA[pb*8704 + rl*68 + (c0>>1)] = pk2(v0, v1);
                }
            }
        __syncthreads();

        if(wid < 4){
            float accC[2][2][4];
            #pragma unroll
            for(int am=0;am<2;am++)
                #pragma unroll
                for(int bn=0;bn<2;bn++)
                    #pragma unroll
                    for(int i=0;i<4;i++) accC[am][bn][i]=0.f;
            const uint32_t smH = uB + (uint32_t)pb*8704u*4u;
            #pragma unroll
            for(int g=0; g<8; g++){
                uint32_t av[2][4], bv[4];
                ldm4(av[0], smH + aB2 + (uint32_t)(g*8)*4u);
                ldm4(av[1], smH + aB2 + (uint32_t)(16*68 + g*8)*4u);
                ldm4(bv, uSC2 + bC2 + (uint32_t)(g*8)*4u);
                #pragma unroll
                for(int am=0;am<2;am++){
                    mma16(accC[am][0], av[am], &bv[0]);
                    mma16(accC[am][1], av[am], &bv[2]);
                }
            }
            float* sCh = (float*)SEF;
            #pragma unroll
            for(int am=0;am<2;am++)
                #pragma unroll
                for(int hf=0;hf<2;hf++){
                    int rl = warpM + am*16 + r4 + hf*8;
                    #pragma unroll
                    for(int bn=0;bn<2;bn++){
                        int c0 = bn*8 + c4*2;
                        sCh[rl*16+c0]   = accC[am][bn][hf*2];
                        sCh[rl*16+c0+1] = accC[am][bn][hf*2+1];
                    }
                }
        }
        __syncthreads();

        if(tid < 128){
            const float* sCh = (const float*)SEF;
            int rl = tid;
            int r = sRow[rl], c = sCol[rl];
            float P[15]; P[0]=0.f;
            #pragma unroll
            for(int j=0;j<14;j++) P[j+1] = P[j] + sCh[rl*16+j] + scb[j];
            int cs = (int)(g_csum[r]+0.5f);
            int w = 15 - cs;
            float invw = 1.f/(float)w;
            float px=g_pool3[c*3], py=g_pool3[c*3+1], pz=g_pool3[c*3+2];
            float vals[42];
            #pragma unroll
            for(int i=0;i<14;i++){
                int e2 = min(i+w, 14);
                float pooled = (P[e2]-P[i])*invw;
                const float* xp = &x[((size_t)r*14+i)*3];
                vals[i*3+0] = (xp[0]-px)*pooled;
                vals[i*3+1] = (xp[1]-py)*pooled;
                vals[i*3+2] = (xp[2]-pz)*pooled;
            }
            float* base = &g_xsum[r*42];
            #pragma unroll
            for(int t=0;t<21;t++) red2(base+2*t, vals[2*t], vals[2*t+1]);
        }
        __syncthreads();
        pb ^= 1;
    }
}

// ===== fused node path =====
#define NODESM 208896
__global__ void __launch_bounds__(256,1) k_node(
    const float* __restrict__ h, const float* __restrict__ n1W,
    const float* __restrict__ n1B, const float* __restrict__ n2W,
    const float* __restrict__ n2B, const float* __restrict__ lng,
    const float* __restrict__ lnb, float* __restrict__ out, int tiles)
{
    extern __shared__ uint32_t dsm[];
    uint32_t* SW1 = dsm;
    uint32_t* SA  = dsm + 17408;
    uint32_t* SW2 = dsm + 34816;
    uint32_t* SH  = dsm + 43520;
    __shared__ float sB1[128], sB2[128], sG[128], sBt[128];
    __shared__ float sSum[256], sSq[256];
    const int tid=threadIdx.x, wid=tid>>5, lane=tid&31;
    const int warpM=(wid&3)*32, warpN=(wid>>2)*64;
    const int r4=lane>>2, c4=lane&3;
    const uint32_t* hbf=(const uint32_t*)g_hbf;

    for(int idx=tid; idx<128*128; idx+=256){
        int kp=idx>>7, n=idx&127;
        SW1[kp*136+n] = pk2(n1W[n*256+2*kp], n1W[n*256+2*kp+1]);
    }
    for(int idx=tid; idx<64*128; idx+=256){
        int kp=idx/128, n=idx%128;
        SW2[kp*136+n] = pk2(n2W[n*128+2*kp], n2W[n*128+2*kp+1]);
    }
    if(tid<128){ sB1[tid]=n1B[tid]; sB2[tid]=n2B[tid]; sG[tid]=lng[tid]; sBt[tid]=lnb[tid]; }
    __syncthreads();

    float acc[2][8][4];
    auto gemmK = [&](const uint32_t* Ab, const uint32_t* Wb, int ng){
        for(int g=0; g<ng; g++){
            uint32_t bfr[8][2];
            #pragma unroll
            for(int bn=0;bn<8;bn++){
                int n = warpN + bn*8 + r4;
                bfr[bn][0] = Wb[(g*8+c4)*136 + n];
                bfr[bn][1] = Wb[(g*8+c4+4)*136 + n];
            }
            #pragma unroll
            for(int am=0;am<2;am++){
                int m0 = warpM + am*16 + r4;
                uint32_t af[4] = { Ab[(g*8+c4)*136+m0], Ab[(g*8+c4)*136+m0+8],
                                   Ab[(g*8+c4+4)*136+m0], Ab[(g*8+c4+4)*136+m0+8] };
                #pragma unroll
                for(int bn=0;bn<8;bn++) mma16(acc[am][bn], af, bfr[bn]);
            }
        }
    };

    for(int tile=blockIdx.x; tile<tiles; tile+=gridDim.x){
        {
            int rl = tid>>1, q = tid&1;
            int n = min(tile*128+rl, NN-1);
            if(q==0){
                const uint4* p = (const uint4*)&hbf[n*64];
                uint32_t* d = &SA[rl];
                #pragma unroll
                for(int j=0;j<16;j++){
                    uint4 u = p[j];
                    d[(j*4+0)*136]=u.x; d[(j*4+1)*136]=u.y;
                    d[(j*4+2)*136]=u.z; d[(j*4+3)*136]=u.w;
                }
            } else {
                float inv = 1.f/fmaxf(g_cnt_col[n],1.f);
                const float4* p = (const float4*)&g_aggsum[(size_t)n*128];
                uint32_t* d = &SA[64*136 + rl];
                #pragma unroll
                for(int j=0;j<32;j++){
                    float4 v = p[j];
                    d[(j*2+0)*136]=pk2(v.x*inv, v.y*inv);
                    d[(j*2+1)*136]=pk2(v.z*inv, v.w*inv);
                }
            }
        }
        __syncthreads();
        #pragma unroll
        for(int am=0;am<2;am++)
            #pragma unroll
            for(int bn=0;bn<8;bn++)
                #pragma unroll
                for(int i=0;i<4;i++) acc[am][bn][i]=0.f;
        gemmK(SA, SW1, 16);
        #pragma unroll
        for(int am=0;am<2;am++)
            #pragma unroll
            for(int hf=0;hf<2;hf++){
                int rl = warpM + am*16 + r4 + hf*8;
                #pragma unroll
                for(int bn=0;bn<8;bn++){
                    int c0 = warpN + bn*8 + c4*2;
                    float v0 = silu_(acc[am][bn][hf*2]   + sB1[c0]);
                    float v1 = silu_(acc[am][bn][hf*2+1] + sB1[c0+1]);
                    SH[(c0>>1)*136 + rl] = pk2(v0, v1);
                }
            }
        __syncthreads();
        #pragma unroll
        for(int am=0;am<2;am++)
            #pragma unroll
            for(int bn=0;bn<8;bn++)
                #pragma unroll
                for(int i=0;i<4;i++) acc[am][bn][i]=0.f;
        gemmK(SH, SW2, 8);
        #pragma unroll
        for(int am=0;am<2;am++)
            #pragma unroll
            for(int hf=0;hf<2;hf++){
                int rl = warpM + am*16 + r4 + hf*8;
                int rg = tile*128 + rl;
                int hn = min(rg, NN-1);
                float s=0.f, sq=0.f;
                #pragma unroll
                for(int bn=0;bn<8;bn++){
                    int c0 = warpN + bn*8 + c4*2;
                    float y0 = acc[am][bn][hf*2]   + sB2[c0]   + h[(size_t)hn*128+c0];
                    float y1 = acc[am][bn][hf*2+1] + sB2[c0+1] + h[(size_t)hn*128+c0+1];
                    acc[am][bn][hf*2]=y0; acc[am][bn][hf*2+1]=y1;
                    s += y0+y1; sq += y0*y0+y1*y1;
                }
                s  += __shfl_xor_sync(0xffffffffu, s, 1);
                s  += __shfl_xor_sync(0xffffffffu, s, 2);
                sq += __shfl_xor_sync(0xffffffffu, sq, 1);
                sq += __shfl_xor_sync(0xffffffffu, sq, 2);
                if(c4==0){
                    sSum[(wid>>2)*128+rl]=s;
                    sSq[(wid>>2)*128+rl]=sq;
                }
            }
        __syncthreads();
        #pragma unroll
        for(int am=0;am<2;am++)
            #pragma unroll
            for(int hf=0;hf<2;hf++){
                int rl = warpM + am*16 + r4 + hf*8;
                int rg = tile*128 + rl;
                if(rg < NN){
                    float tot = sSum[rl]+sSum[128+rl];
                    float mu = tot*(1.f/128.f);
                    float var = (sSq[rl]+sSq[128+rl])*(1.f/128.f) - mu*mu;
                    float is = rsqrtf(fmaxf(var,0.f)+1e-5f);
                    float* op = &out[(size_t)rg*128];
                    #pragma unroll
                    for(int bn=0;bn<8;bn++){
                        int c0 = warpN + bn*8 + c4*2;
                        op[c0]   = (acc[am][bn][hf*2]  -mu)*is*sG[c0]  +sBt[c0];
                        op[c0+1] = (acc[am][bn][hf*2+1]-mu)*is*sG[c0+1]+sBt[c0+1];
                    }
                }
            }
        __syncthreads();
    }
}

// ---------------- x_out ----------------
__global__ void k_xout(const float* __restrict__ x, float* __restrict__ xout){
    int idx = blockIdx.x*blockDim.x + threadIdx.x;
    if(idx >= NN*CC*3) return;
    int n = idx/(CC*3);
    xout[idx] = x[idx] + g_xsum[idx]/fmaxf(g_cnt_row[n],1.f);
}

// ======================= host launcher =======================
extern "C" void kernel_launch(void* const* d_in, const int* in_sizes, int n_in,
                              void* d_out, int out_size){
    const float* h    = (const float*)d_in[0];
    const float* x    = (const float*)d_in[1];
    const int*   row  = (const int*)  d_in[2];
    const int*   col  = (const int*)  d_in[3];
    const float* attr = (const float*)d_in[4];
    const float* cw   = (const float*)d_in[5];
    const float* radW = (const float*)d_in[6];  const float* radB = (const float*)d_in[7];
    const float* e1W  = (const float*)d_in[8];  const float* e1B  = (const float*)d_in[9];
    const float* e2W  = (const float*)d_in[10]; const float* e2B  = (const float*)d_in[11];
    const float* attW = (const float*)d_in[12]; const float* attB = (const float*)d_in[13];
    const float* c1W  = (const float*)d_in[14]; const float* c1B  = (const float*)d_in[15];
    const float* c2W  = (const float*)d_in[16]; const float* c2B  = (const float*)d_in[17];
    const float* n1W  = (const float*)d_in[18]; const float* n1B  = (const float*)d_in[19];
    const float* n2W  = (const float*)d_in[20]; const float* n2B  = (const float*)d_in[21];
    const float* lng  = (const float*)d_in[22]; const float* lnb  = (const float*)d_in[23];
    float* outH = (float*)d_out;
    float* outX = outH + (size_t)NN*128;

    void *p_agg,*p_cntc;
    cudaGetSymbolAddress(&p_agg,  g_aggsum);
    cudaGetSymbolAddress(&p_cntc, g_cnt_col);

    cudaFuncSetAttribute(k_e1,   cudaFuncAttributeMaxDynamicSharedMemorySize, E1SM);
    cudaFuncSetAttribute(k_e2c1, cudaFuncAttributeMaxDynamicSharedMemorySize, E2SM);
    cudaFuncSetAttribute(k_node, cudaFuncAttributeMaxDynamicSharedMemorySize, NODESM);

    k_prepall<<<(int)((PREP_TOTAL+255)/256), 256>>>(x, cw, h, attr, e2W, c1W);
    k_waug<<<128, 256>>>(e1W, radW, radB);
    k_geom<<<NE/8, 256>>>(x, row, col, cw);

    k_e1<<<304,256,E1SM>>>(e1B, row, col, TE128);
    k_e2c1<<<148,256,E2SM>>>(e2B, c1B, c2W, c2B, row, col, attW, attB,
                             x, (float*)p_agg, (float*)p_cntc, TE128);
    k_node<<<TN128,256,NODESM>>>(h, n1W, n1B, n2W, n2B, lng, lnb, outH, TN128);
    k_xout<<<(NN*CC*3+255)/256, 256>>>(x, outX);
}